// round 6
// baseline (speedup 1.0000x reference)
#include <cuda_runtime.h>
#include <cuda.h>
#include <cuda_fp16.h>
#include <cstdint>

#define NNB 32
#define CI  128
#define CO  256
#define HH  56
#define WW  56

// Padded NHWC x in fp16: [n][59 rows][64 cols][128 ci]; rows 1..56 = h 0..55,
// cols 0..55 = w, all padding zero. 128-half front guard for the (h0=0, col -1) read.
__device__ __align__(256) __half g_xt[128 + (size_t)NNB * 59 * 64 * CI];
__device__ __align__(256) __half g_wt[9 * CO * CI];   // [tap][co][ci]

// ---------------- helpers ----------------
__device__ __forceinline__ void cp_async16(uint32_t dst_smem, const void* src) {
    asm volatile("cp.async.cg.shared.global [%0], [%1], 16;" :: "r"(dst_smem), "l"(src) : "memory");
}
#define CP_COMMIT() asm volatile("cp.async.commit_group;" ::: "memory")
#define CP_WAIT0()  asm volatile("cp.async.wait_group 0;" ::: "memory")

#define LDM_X4(r0, r1, r2, r3, addr) \
    asm volatile("ldmatrix.sync.aligned.m8n8.x4.shared.b16 {%0,%1,%2,%3}, [%4];" \
        : "=r"(r0), "=r"(r1), "=r"(r2), "=r"(r3) : "r"(addr))

__device__ __forceinline__ void mma_f16(float d[4], const uint32_t a[4], uint32_t b0, uint32_t b1) {
    asm volatile(
        "mma.sync.aligned.m16n8k16.row.col.f32.f16.f16.f32 "
        "{%0,%1,%2,%3}, {%4,%5,%6,%7}, {%8,%9}, {%0,%1,%2,%3};"
        : "+f"(d[0]), "+f"(d[1]), "+f"(d[2]), "+f"(d[3])
        : "r"(a[0]), "r"(a[1]), "r"(a[2]), "r"(a[3]), "r"(b0), "r"(b1));
}

// ---------------- prologue ----------------
// One block per (padded row h_p, n). Writes the FULL 64x128-half padded row
// (zeros included) with 16B stores. Block (0,0) also zeros the front guard.
__global__ __launch_bounds__(256)
void xpose_kernel(const float* __restrict__ x) {
    __shared__ float s[128][57];
    const int h_p = blockIdx.x;     // 0..58
    const int n   = blockIdx.y;
    const int tid = threadIdx.x;
    const int h   = h_p - 1;
    const bool valid = (h >= 0) && (h < HH);

    if (h_p == 0 && n == 0 && tid < 16)   // front guard (row "-1" of n=0)
        *(uint4*)(g_xt + tid * 8) = make_uint4(0u, 0u, 0u, 0u);

    if (valid) {
        const float* base = x + ((size_t)n * CI * HH + h) * WW;
        for (int idx = tid; idx < CI * 14; idx += 256) {   // 14 float4 per row
            int ci = idx / 14, j = idx % 14;
            float4 v = *(const float4*)(base + (size_t)ci * HH * WW + 4 * j);
            s[ci][4 * j]     = v.x;
            s[ci][4 * j + 1] = v.y;
            s[ci][4 * j + 2] = v.z;
            s[ci][4 * j + 3] = v.w;
        }
    }
    __syncthreads();

    __half* dst = g_xt + 128 + (size_t)(n * 59 + h_p) * 64 * CI;
    for (int idx = tid; idx < 64 * 16; idx += 256) {
        const int w = idx >> 4;         // 0..63
        const int g = idx & 15;         // ci group of 8
        uint4 v = make_uint4(0u, 0u, 0u, 0u);
        if (valid && w < WW) {
            __half2 p0 = __floats2half2_rn(s[g * 8 + 0][w], s[g * 8 + 1][w]);
            __half2 p1 = __floats2half2_rn(s[g * 8 + 2][w], s[g * 8 + 3][w]);
            __half2 p2 = __floats2half2_rn(s[g * 8 + 4][w], s[g * 8 + 5][w]);
            __half2 p3 = __floats2half2_rn(s[g * 8 + 6][w], s[g * 8 + 7][w]);
            v.x = *(uint32_t*)&p0; v.y = *(uint32_t*)&p1;
            v.z = *(uint32_t*)&p2; v.w = *(uint32_t*)&p3;
        }
        *(uint4*)(dst + (size_t)w * CI + g * 8) = v;
    }
}

__global__ void wxform_kernel(const float* __restrict__ wgt) {
    int idx = blockIdx.x * 256 + threadIdx.x;
    if (idx >= 9 * CO * CI) return;
    int ci  = idx % CI;
    int t   = idx / CI;
    int co  = t % CO;
    int tap = t / CO;
    g_wt[idx] = __float2half_rn(wgt[((size_t)co * CI + ci) * 9 + tap]);
}

// ---------------- main kernel ----------------
// CTA: 128 co x 128 px (2 out rows x 64 padded w).
// B: resident 258-row x 64ci x 2 halves window (66KB), loaded ONCE.
//    Tap (r,s) = row offset r*64+s into the window.
// A: 18 chunks (tap x ci-half, 16KB each), double-buffered cp.async; prefetch
//    for chunk kc+1 issued at the TOP of chunk kc (full-chunk latency cover).
constexpr int B_HALF_BYTES = 258 * 128;              // 33024
constexpr int B_BYTES      = 2 * B_HALF_BYTES;       // 66048
constexpr int A_TILE       = 128 * 64 * 2;           // 16384
constexpr int SMEM_BYTES   = B_BYTES + 2 * A_TILE;   // 98816

__global__ __launch_bounds__(256, 2)
void conv_mma_kernel(float* __restrict__ out)
{
    extern __shared__ char smem[];
    const uint32_t sm_u = (uint32_t)__cvta_generic_to_shared(smem);
    const uint32_t B_u  = sm_u;
    const uint32_t A_u  = sm_u + B_BYTES;

    const int tid  = threadIdx.x;
    const int lane = tid & 31;
    const int warp = tid >> 5;
    const int g    = lane >> 2;
    const int t    = lane & 3;
    const int warp_m = (warp >> 1) * 32;   // 4 warps in m
    const int warp_n = (warp & 1) * 64;    // 2 warps in n

    const int co_base = blockIdx.x * 128;
    const int h0      = blockIdx.y * 2;
    const int n       = blockIdx.z;

    const __half* xb = g_xt + 128;

    const int quad  = lane >> 3;
    const int rowin = lane & 7;
    const int qlow  = quad & 1;
    const int qhigh = quad >> 1;

    uint32_t aRowB[2];
    #pragma unroll
    for (int mi = 0; mi < 2; mi++)
        aRowB[mi] = (uint32_t)(warp_m + mi * 16 + qlow * 8 + rowin) * 128u;

    float acc[2][8][4];
    #pragma unroll
    for (int mi = 0; mi < 2; mi++)
        #pragma unroll
        for (int ni = 0; ni < 8; ni++)
            #pragma unroll
            for (int r = 0; r < 4; r++) acc[mi][ni][r] = 0.0f;

    // ---- B preload: contiguous 258-row slice starting at flat row (n*59+h0)*64 - 1
    {
        const long long F0 = ((long long)(n * 59 + h0) * 64 - 1) * CI;  // halves
        #pragma unroll
        for (int half = 0; half < 2; half++) {
            const __half* src = xb + F0 + half * 64;
            const uint32_t dstb = B_u + half * B_HALF_BYTES;
            for (int idx = tid; idx < 258 * 8; idx += 256) {
                const int i = idx >> 3, c = idx & 7;
                cp_async16(dstb + (uint32_t)i * 128u + (uint32_t)((c ^ (i & 7)) * 16),
                           src + (size_t)i * CI + c * 8);
            }
        }
    }

    // ---- A chunk loader (tap = kc>>1, ci-half = kc&1) into slot kc&1
    auto loadA = [&](int kc) {
        const int tap = kc >> 1, cihalf = kc & 1;
        const __half* src = g_wt + (size_t)(tap * CO + co_base) * CI + cihalf * 64;
        const uint32_t dA = A_u + (kc & 1) * A_TILE;
        #pragma unroll
        for (int i = 0; i < 4; i++) {
            const int q = tid + 256 * i;
            const int row = q >> 3, c = q & 7;
            cp_async16(dA + (uint32_t)row * 128u + (uint32_t)((c ^ (row & 7)) * 16),
                       src + (size_t)row * CI + c * 8);
        }
    };

    loadA(0);
    CP_COMMIT();

    #pragma unroll
    for (int kc = 0; kc < 18; kc++) {
        const int tap = kc >> 1, cihalf = kc & 1;
        const int r = tap / 3, s = tap % 3;
        const int off = r * 64 + s;           // tap row offset into B window

        CP_WAIT0();                           // waits A slot kc&1 (+B on kc==0)
        __syncthreads();

        // Prefetch next A now: slot (kc+1)&1 was last read in chunk kc-1,
        // and every warp has passed that point (the sync above).
        if (kc + 1 < 18) { loadA(kc + 1); CP_COMMIT(); }

        const uint32_t A  = A_u + (kc & 1) * A_TILE;
        const uint32_t Bb = B_u + cihalf * B_HALF_BYTES;
        const int ro = (rowin + off) & 7;

        uint32_t bBase[4];
        #pragma unroll
        for (int p = 0; p < 4; p++)
            bBase[p] = Bb + (uint32_t)(warp_n + (p * 2 + qhigh) * 8 + rowin + off) * 128u;

        #pragma unroll
        for (int kk = 0; kk < 4; kk++) {
            uint32_t a[2][4];
            #pragma unroll
            for (int mi = 0; mi < 2; mi++)
                LDM_X4(a[mi][0], a[mi][1], a[mi][2], a[mi][3],
                       A + aRowB[mi] + (uint32_t)(((kk * 2 + qhigh) ^ rowin) * 16));
            #pragma unroll
            for (int p = 0; p < 4; p++) {
                uint32_t b0, b1, b2, b3;
                LDM_X4(b0, b1, b2, b3,
                       bBase[p] + (uint32_t)(((kk * 2 + qlow) ^ ro) * 16));
                mma_f16(acc[0][2 * p],     a[0], b0, b1);
                mma_f16(acc[1][2 * p],     a[1], b0, b1);
                mma_f16(acc[0][2 * p + 1], a[0], b2, b3);
                mma_f16(acc[1][2 * p + 1], a[1], b2, b3);
            }
        }
    }

    // ---- epilogue: c0/c1 adjacent px -> float2 stores
    #pragma unroll
    for (int mi = 0; mi < 2; mi++)
        #pragma unroll
        for (int ni = 0; ni < 8; ni++)
            #pragma unroll
            for (int half = 0; half < 2; half++) {
                const int co = co_base + warp_m + mi * 16 + g + half * 8;
                const int px = warp_n + ni * 8 + 2 * t;
                const int hh = h0 + (px >> 6);
                const int w  = px & 63;
                if (w < 56) {
                    float2 v = make_float2(acc[mi][ni][half * 2], acc[mi][ni][half * 2 + 1]);
                    *(float2*)&out[(((size_t)n * CO + co) * HH + hh) * WW + w] = v;
                }
            }
}

// ---------------- host ----------------
extern "C" void kernel_launch(void* const* d_in, const int* in_sizes, int n_in,
                              void* d_out, int out_size)
{
    const float* x   = (const float*)d_in[0];
    const float* wgt = (const float*)d_in[1];
    float*       out = (float*)d_out;

    // Exactly 3 launches per invocation so ncu (-s 5 -c 1) captures conv_mma_kernel.
    xpose_kernel<<<dim3(59, NNB), 256>>>(x);
    wxform_kernel<<<(9 * CO * CI + 255) / 256, 256>>>(wgt);

    cudaFuncSetAttribute(conv_mma_kernel, cudaFuncAttributeMaxDynamicSharedMemorySize, SMEM_BYTES);
    conv_mma_kernel<<<dim3(2, 28, NNB), 256, SMEM_BYTES>>>(out);
}

// round 7
// speedup vs baseline: 1.5195x; 1.5195x over previous
#include <cuda_runtime.h>
#include <cuda.h>
#include <cuda_fp16.h>
#include <cstdint>

#define NNB 32
#define CI  128
#define CO  256
#define HH  56
#define WW  56

// Padded NHWC x in fp16: [n][59 rows][64 cols][128 ci]; rows 1..56 = h 0..55,
// cols 0..55 = w, all padding zero. 128-half front guard for the (h0=0, col -1) read.
__device__ __align__(256) __half g_xt[128 + (size_t)NNB * 59 * 64 * CI];
__device__ __align__(256) __half g_wt[9 * CO * CI];   // [tap][co][ci]

// ---------------- helpers ----------------
__device__ __forceinline__ void cp_async16(uint32_t dst_smem, const void* src) {
    asm volatile("cp.async.cg.shared.global [%0], [%1], 16;" :: "r"(dst_smem), "l"(src) : "memory");
}
#define CP_COMMIT() asm volatile("cp.async.commit_group;" ::: "memory")
#define CP_WAIT0()  asm volatile("cp.async.wait_group 0;" ::: "memory")

#define LDM_X4(r0, r1, r2, r3, addr) \
    asm volatile("ldmatrix.sync.aligned.m8n8.x4.shared.b16 {%0,%1,%2,%3}, [%4];" \
        : "=r"(r0), "=r"(r1), "=r"(r2), "=r"(r3) : "r"(addr))

__device__ __forceinline__ void mma_f16(float d[4], const uint32_t a[4], uint32_t b0, uint32_t b1) {
    asm volatile(
        "mma.sync.aligned.m16n8k16.row.col.f32.f16.f16.f32 "
        "{%0,%1,%2,%3}, {%4,%5,%6,%7}, {%8,%9}, {%0,%1,%2,%3};"
        : "+f"(d[0]), "+f"(d[1]), "+f"(d[2]), "+f"(d[3])
        : "r"(a[0]), "r"(a[1]), "r"(a[2]), "r"(a[3]), "r"(b0), "r"(b1));
}

// ---------------- prologue ----------------
// Round-5 xpose (scalar reads — fastest measured) + front-guard zeroing.
__global__ __launch_bounds__(256)
void xpose_kernel(const float* __restrict__ x) {
    __shared__ float s[128][57];
    const int h_p = blockIdx.x;     // 0..58
    const int n   = blockIdx.y;
    const int tid = threadIdx.x;
    const int h   = h_p - 1;
    const bool valid = (h >= 0) && (h < HH);

    if (h_p == 0 && n == 0 && tid < 16)   // front guard (row "-1" of n=0)
        *(uint4*)(g_xt + tid * 8) = make_uint4(0u, 0u, 0u, 0u);

    if (valid) {
        for (int idx = tid; idx < CI * WW; idx += 256) {
            int ci = idx / WW, w = idx % WW;
            s[ci][w] = x[(((size_t)n * CI + ci) * HH + h) * WW + w];
        }
    }
    __syncthreads();

    __half* dst = g_xt + 128 + (size_t)(n * 59 + h_p) * 64 * CI;
    for (int idx = tid; idx < 64 * 16; idx += 256) {
        const int w = idx >> 4;         // 0..63
        const int g = idx & 15;         // ci group of 8
        uint4 v = make_uint4(0u, 0u, 0u, 0u);
        if (valid && w < WW) {
            __half2 p0 = __floats2half2_rn(s[g * 8 + 0][w], s[g * 8 + 1][w]);
            __half2 p1 = __floats2half2_rn(s[g * 8 + 2][w], s[g * 8 + 3][w]);
            __half2 p2 = __floats2half2_rn(s[g * 8 + 4][w], s[g * 8 + 5][w]);
            __half2 p3 = __floats2half2_rn(s[g * 8 + 6][w], s[g * 8 + 7][w]);
            v.x = *(uint32_t*)&p0; v.y = *(uint32_t*)&p1;
            v.z = *(uint32_t*)&p2; v.w = *(uint32_t*)&p3;
        }
        *(uint4*)(dst + (size_t)w * CI + g * 8) = v;
    }
}

__global__ void wxform_kernel(const float* __restrict__ wgt) {
    int idx = blockIdx.x * 256 + threadIdx.x;
    if (idx >= 9 * CO * CI) return;
    int ci  = idx % CI;
    int t   = idx / CI;
    int co  = t % CO;
    int tap = t / CO;
    g_wt[idx] = __float2half_rn(wgt[((size_t)co * CI + ci) * 9 + tap]);
}

// ---------------- main kernel (round-5 structure: prefetch at kk==1) ----------------
constexpr int B_HALF_BYTES = 258 * 128;              // 33024
constexpr int B_BYTES      = 2 * B_HALF_BYTES;       // 66048
constexpr int A_TILE       = 128 * 64 * 2;           // 16384
constexpr int SMEM_BYTES   = B_BYTES + 2 * A_TILE;   // 98816

__global__ __launch_bounds__(256, 2)
void conv_mma_kernel(float* __restrict__ out)
{
    extern __shared__ char smem[];
    const uint32_t sm_u = (uint32_t)__cvta_generic_to_shared(smem);
    const uint32_t B_u  = sm_u;
    const uint32_t A_u  = sm_u + B_BYTES;

    const int tid  = threadIdx.x;
    const int lane = tid & 31;
    const int warp = tid >> 5;
    const int g    = lane >> 2;
    const int t    = lane & 3;
    const int warp_m = (warp >> 1) * 32;   // 4 warps in m
    const int warp_n = (warp & 1) * 64;    // 2 warps in n

    const int co_base = blockIdx.x * 128;
    const int h0      = blockIdx.y * 2;
    const int n       = blockIdx.z;

    const __half* xb = g_xt + 128;

    const int quad  = lane >> 3;
    const int rowin = lane & 7;
    const int qlow  = quad & 1;
    const int qhigh = quad >> 1;

    uint32_t aRowB[2];
    #pragma unroll
    for (int mi = 0; mi < 2; mi++)
        aRowB[mi] = (uint32_t)(warp_m + mi * 16 + qlow * 8 + rowin) * 128u;

    float acc[2][8][4];
    #pragma unroll
    for (int mi = 0; mi < 2; mi++)
        #pragma unroll
        for (int ni = 0; ni < 8; ni++)
            #pragma unroll
            for (int r = 0; r < 4; r++) acc[mi][ni][r] = 0.0f;

    // ---- B preload: contiguous 258-row slice starting at flat row (n*59+h0)*64 - 1
    {
        const long long F0 = ((long long)(n * 59 + h0) * 64 - 1) * CI;  // halves
        #pragma unroll
        for (int half = 0; half < 2; half++) {
            const __half* src = xb + F0 + half * 64;
            const uint32_t dstb = B_u + half * B_HALF_BYTES;
            for (int idx = tid; idx < 258 * 8; idx += 256) {
                const int i = idx >> 3, c = idx & 7;
                cp_async16(dstb + (uint32_t)i * 128u + (uint32_t)((c ^ (i & 7)) * 16),
                           src + (size_t)i * CI + c * 8);
            }
        }
    }

    // ---- A chunk loader (tap = kc>>1, ci-half = kc&1) into slot kc&1
    auto loadA = [&](int kc) {
        const int tap = kc >> 1, cihalf = kc & 1;
        const __half* src = g_wt + (size_t)(tap * CO + co_base) * CI + cihalf * 64;
        const uint32_t dA = A_u + (kc & 1) * A_TILE;
        #pragma unroll
        for (int i = 0; i < 4; i++) {
            const int q = tid + 256 * i;
            const int row = q >> 3, c = q & 7;
            cp_async16(dA + (uint32_t)row * 128u + (uint32_t)((c ^ (row & 7)) * 16),
                       src + (size_t)row * CI + c * 8);
        }
    };

    loadA(0);
    CP_COMMIT();

    #pragma unroll
    for (int kc = 0; kc < 18; kc++) {
        const int tap = kc >> 1, cihalf = kc & 1;
        const int r = tap / 3, s = tap % 3;
        const int off = r * 64 + s;           // tap row offset into B window

        CP_WAIT0();
        __syncthreads();

        const uint32_t A  = A_u + (kc & 1) * A_TILE;
        const uint32_t Bb = B_u + cihalf * B_HALF_BYTES;
        const int ro = (rowin + off) & 7;

        uint32_t bBase[4];
        #pragma unroll
        for (int p = 0; p < 4; p++)
            bBase[p] = Bb + (uint32_t)(warp_n + (p * 2 + qhigh) * 8 + rowin + off) * 128u;

        #pragma unroll
        for (int kk = 0; kk < 4; kk++) {
            uint32_t a[2][4];
            #pragma unroll
            for (int mi = 0; mi < 2; mi++)
                LDM_X4(a[mi][0], a[mi][1], a[mi][2], a[mi][3],
                       A + aRowB[mi] + (uint32_t)(((kk * 2 + qhigh) ^ rowin) * 16));
            #pragma unroll
            for (int p = 0; p < 4; p++) {
                uint32_t b0, b1, b2, b3;
                LDM_X4(b0, b1, b2, b3,
                       bBase[p] + (uint32_t)(((kk * 2 + qlow) ^ ro) * 16));
                mma_f16(acc[0][2 * p],     a[0], b0, b1);
                mma_f16(acc[1][2 * p],     a[1], b0, b1);
                mma_f16(acc[0][2 * p + 1], a[0], b2, b3);
                mma_f16(acc[1][2 * p + 1], a[1], b2, b3);
            }
            if (kk == 1) {                      // prefetch next A mid-compute
                if (kc + 1 < 18) loadA(kc + 1);
                CP_COMMIT();
            }
        }
        __syncthreads();
    }

    // ---- epilogue: c0/c1 adjacent px -> float2 stores
    #pragma unroll
    for (int mi = 0; mi < 2; mi++)
        #pragma unroll
        for (int ni = 0; ni < 8; ni++)
            #pragma unroll
            for (int half = 0; half < 2; half++) {
                const int co = co_base + warp_m + mi * 16 + g + half * 8;
                const int px = warp_n + ni * 8 + 2 * t;
                const int hh = h0 + (px >> 6);
                const int w  = px & 63;
                if (w < 56) {
                    float2 v = make_float2(acc[mi][ni][half * 2], acc[mi][ni][half * 2 + 1]);
                    *(float2*)&out[(((size_t)n * CO + co) * HH + hh) * WW + w] = v;
                }
            }
}

// ---------------- host ----------------
extern "C" void kernel_launch(void* const* d_in, const int* in_sizes, int n_in,
                              void* d_out, int out_size)
{
    const float* x   = (const float*)d_in[0];
    const float* wgt = (const float*)d_in[1];
    float*       out = (float*)d_out;

    // Exactly 3 launches per invocation so ncu (-s 5 -c 1) captures conv_mma_kernel.
    xpose_kernel<<<dim3(59, NNB), 256>>>(x);
    wxform_kernel<<<(9 * CO * CI + 255) / 256, 256>>>(wgt);

    cudaFuncSetAttribute(conv_mma_kernel, cudaFuncAttributeMaxDynamicSharedMemorySize, SMEM_BYTES);
    conv_mma_kernel<<<dim3(2, 28, NNB), 256, SMEM_BYTES>>>(out);
}

// round 8
// speedup vs baseline: 1.5772x; 1.0379x over previous
#include <cuda_runtime.h>
#include <cuda.h>
#include <cuda_fp16.h>
#include <cstdint>

#define NNB 32
#define CI  128
#define CO  256
#define HH  56
#define WW  56

// Padded NHWC x in fp16: [n][59 rows][64 cols][128 ci]; rows 1..56 = h 0..55,
// cols 0..55 = w, all padding zero. 128-half front guard for the (h0=0, col -1) read.
__device__ __align__(256) __half g_xt[128 + (size_t)NNB * 59 * 64 * CI];
__device__ __align__(256) __half g_wt[9 * CO * CI];   // [tap][co][ci]

// ---------------- helpers ----------------
__device__ __forceinline__ void cp_async16(uint32_t dst_smem, const void* src) {
    asm volatile("cp.async.cg.shared.global [%0], [%1], 16;" :: "r"(dst_smem), "l"(src) : "memory");
}
#define CP_COMMIT() asm volatile("cp.async.commit_group;" ::: "memory")
#define CP_WAIT0()  asm volatile("cp.async.wait_group 0;" ::: "memory")

#define LDM_X4(r0, r1, r2, r3, addr) \
    asm volatile("ldmatrix.sync.aligned.m8n8.x4.shared.b16 {%0,%1,%2,%3}, [%4];" \
        : "=r"(r0), "=r"(r1), "=r"(r2), "=r"(r3) : "r"(addr))

__device__ __forceinline__ void mma_f16(float d[4], const uint32_t a[4], uint32_t b0, uint32_t b1) {
    asm volatile(
        "mma.sync.aligned.m16n8k16.row.col.f32.f16.f16.f32 "
        "{%0,%1,%2,%3}, {%4,%5,%6,%7}, {%8,%9}, {%0,%1,%2,%3};"
        : "+f"(d[0]), "+f"(d[1]), "+f"(d[2]), "+f"(d[3])
        : "r"(a[0]), "r"(a[1]), "r"(a[2]), "r"(a[3]), "r"(b0), "r"(b1));
}

// ---------------- fused prologue ----------------
// blockIdx.x < 59: x transpose rows (round-5 form). blockIdx.x == 59: weight xform.
__global__ __launch_bounds__(256)
void prologue_kernel(const float* __restrict__ x, const float* __restrict__ wgt) {
    const int tid = threadIdx.x;
    const int n   = blockIdx.y;

    if (blockIdx.x == 59) {   // weights: 32 blocks x 256 thr cover 9*256*128
        const int base = n * (9 * CO * CI / NNB);
        for (int k = 0; k < 9 * CO * CI / NNB; k += 256) {
            int idx = base + k + tid;
            int ci  = idx % CI;
            int t   = idx / CI;
            int co  = t % CO;
            int tap = t / CO;
            g_wt[idx] = __float2half_rn(wgt[((size_t)co * CI + ci) * 9 + tap]);
        }
        return;
    }

    __shared__ float s[128][57];
    const int h_p = blockIdx.x;     // 0..58
    const int h   = h_p - 1;
    const bool valid = (h >= 0) && (h < HH);

    if (h_p == 0 && n == 0 && tid < 16)   // front guard (row "-1" of n=0)
        *(uint4*)(g_xt + tid * 8) = make_uint4(0u, 0u, 0u, 0u);

    if (valid) {
        for (int idx = tid; idx < CI * WW; idx += 256) {
            int ci = idx / WW, w = idx % WW;
            s[ci][w] = x[(((size_t)n * CI + ci) * HH + h) * WW + w];
        }
    }
    __syncthreads();

    __half* dst = g_xt + 128 + (size_t)(n * 59 + h_p) * 64 * CI;
    for (int idx = tid; idx < 64 * 16; idx += 256) {
        const int w = idx >> 4;
        const int g = idx & 15;
        uint4 v = make_uint4(0u, 0u, 0u, 0u);
        if (valid && w < WW) {
            __half2 p0 = __floats2half2_rn(s[g * 8 + 0][w], s[g * 8 + 1][w]);
            __half2 p1 = __floats2half2_rn(s[g * 8 + 2][w], s[g * 8 + 3][w]);
            __half2 p2 = __floats2half2_rn(s[g * 8 + 4][w], s[g * 8 + 5][w]);
            __half2 p3 = __floats2half2_rn(s[g * 8 + 6][w], s[g * 8 + 7][w]);
            v.x = *(uint32_t*)&p0; v.y = *(uint32_t*)&p1;
            v.z = *(uint32_t*)&p2; v.w = *(uint32_t*)&p3;
        }
        *(uint4*)(dst + (size_t)w * CI + g * 8) = v;
    }
}

// ---------------- main kernel ----------------
// CTA: 128 co x 128 px (2 out rows x 64 padded w), 128 threads.
// 4 warps = 2m x 2n, warp tile 64x64: per chunk 32 LDSM vs 128 HMMA.
// B: resident 258-row window (66KB) loaded once; tap (r,s) = row offset r*64+s.
// A: 18 chunks (16KB), double-buffered cp.async, prefetch at kk==1.
constexpr int B_HALF_BYTES = 258 * 128;              // 33024
constexpr int B_BYTES      = 2 * B_HALF_BYTES;       // 66048
constexpr int A_TILE       = 128 * 64 * 2;           // 16384
constexpr int SMEM_BYTES   = B_BYTES + 2 * A_TILE;   // 98816

__global__ __launch_bounds__(128, 2)
void conv_mma_kernel(float* __restrict__ out)
{
    extern __shared__ char smem[];
    const uint32_t sm_u = (uint32_t)__cvta_generic_to_shared(smem);
    const uint32_t B_u  = sm_u;
    const uint32_t A_u  = sm_u + B_BYTES;

    const int tid  = threadIdx.x;
    const int lane = tid & 31;
    const int warp = tid >> 5;
    const int g    = lane >> 2;
    const int t    = lane & 3;
    const int warp_m = (warp >> 1) * 64;   // 2 warps in m
    const int warp_n = (warp & 1) * 64;    // 2 warps in n

    const int co_base = blockIdx.x * 128;
    const int h0      = blockIdx.y * 2;
    const int n       = blockIdx.z;

    const __half* xb = g_xt + 128;

    const int quad  = lane >> 3;
    const int rowin = lane & 7;
    const int qlow  = quad & 1;
    const int qhigh = quad >> 1;

    uint32_t aRowB[4];
    #pragma unroll
    for (int mi = 0; mi < 4; mi++)
        aRowB[mi] = (uint32_t)(warp_m + mi * 16 + qlow * 8 + rowin) * 128u;

    float acc[4][8][4];
    #pragma unroll
    for (int mi = 0; mi < 4; mi++)
        #pragma unroll
        for (int ni = 0; ni < 8; ni++)
            #pragma unroll
            for (int r = 0; r < 4; r++) acc[mi][ni][r] = 0.0f;

    // ---- B preload: contiguous 258-row slice starting at flat row (n*59+h0)*64 - 1
    {
        const long long F0 = ((long long)(n * 59 + h0) * 64 - 1) * CI;  // halves
        #pragma unroll
        for (int half = 0; half < 2; half++) {
            const __half* src = xb + F0 + half * 64;
            const uint32_t dstb = B_u + half * B_HALF_BYTES;
            for (int idx = tid; idx < 258 * 8; idx += 128) {
                const int i = idx >> 3, c = idx & 7;
                cp_async16(dstb + (uint32_t)i * 128u + (uint32_t)((c ^ (i & 7)) * 16),
                           src + (size_t)i * CI + c * 8);
            }
        }
    }

    // ---- A chunk loader (tap = kc>>1, ci-half = kc&1) into slot kc&1
    auto loadA = [&](int kc) {
        const int tap = kc >> 1, cihalf = kc & 1;
        const __half* src = g_wt + (size_t)(tap * CO + co_base) * CI + cihalf * 64;
        const uint32_t dA = A_u + (kc & 1) * A_TILE;
        #pragma unroll
        for (int i = 0; i < 8; i++) {
            const int q = tid + 128 * i;
            const int row = q >> 3, c = q & 7;
            cp_async16(dA + (uint32_t)row * 128u + (uint32_t)((c ^ (row & 7)) * 16),
                       src + (size_t)row * CI + c * 8);
        }
    };

    loadA(0);
    CP_COMMIT();

    #pragma unroll
    for (int kc = 0; kc < 18; kc++) {
        const int tap = kc >> 1, cihalf = kc & 1;
        const int r = tap / 3, s = tap % 3;
        const int off = r * 64 + s;           // tap row offset into B window

        CP_WAIT0();
        __syncthreads();

        const uint32_t A  = A_u + (kc & 1) * A_TILE;
        const uint32_t Bb = B_u + cihalf * B_HALF_BYTES;
        const int ro = (rowin + off) & 7;

        uint32_t bBase[4];
        #pragma unroll
        for (int p = 0; p < 4; p++)
            bBase[p] = Bb + (uint32_t)(warp_n + (p * 2 + qhigh) * 8 + rowin + off) * 128u;

        #pragma unroll
        for (int kk = 0; kk < 4; kk++) {
            uint32_t a[4][4];
            #pragma unroll
            for (int mi = 0; mi < 4; mi++)
                LDM_X4(a[mi][0], a[mi][1], a[mi][2], a[mi][3],
                       A + aRowB[mi] + (uint32_t)(((kk * 2 + qhigh) ^ rowin) * 16));
            #pragma unroll
            for (int p = 0; p < 4; p++) {
                uint32_t b0, b1, b2, b3;
                LDM_X4(b0, b1, b2, b3,
                       bBase[p] + (uint32_t)(((kk * 2 + qlow) ^ ro) * 16));
                #pragma unroll
                for (int mi = 0; mi < 4; mi++) {
                    mma_f16(acc[mi][2 * p],     a[mi], b0, b1);
                    mma_f16(acc[mi][2 * p + 1], a[mi], b2, b3);
                }
            }
            if (kk == 1) {                      // prefetch next A mid-compute
                if (kc + 1 < 18) loadA(kc + 1);
                CP_COMMIT();
            }
        }
        __syncthreads();
    }

    // ---- epilogue: c0/c1 adjacent px -> float2 stores
    #pragma unroll
    for (int mi = 0; mi < 4; mi++)
        #pragma unroll
        for (int ni = 0; ni < 8; ni++)
            #pragma unroll
            for (int half = 0; half < 2; half++) {
                const int co = co_base + warp_m + mi * 16 + g + half * 8;
                const int px = warp_n + ni * 8 + 2 * t;
                const int hh = h0 + (px >> 6);
                const int w  = px & 63;
                if (w < 56) {
                    float2 v = make_float2(acc[mi][ni][half * 2], acc[mi][ni][half * 2 + 1]);
                    *(float2*)&out[(((size_t)n * CO + co) * HH + hh) * WW + w] = v;
                }
            }
}

// ---------------- host ----------------
extern "C" void kernel_launch(void* const* d_in, const int* in_sizes, int n_in,
                              void* d_out, int out_size)
{
    const float* x   = (const float*)d_in[0];
    const float* wgt = (const float*)d_in[1];
    float*       out = (float*)d_out;

    // Exactly 2 launches per invocation (even launches = conv_mma_kernel).
    prologue_kernel<<<dim3(60, NNB), 256>>>(x, wgt);

    cudaFuncSetAttribute(conv_mma_kernel, cudaFuncAttributeMaxDynamicSharedMemorySize, SMEM_BYTES);
    conv_mma_kernel<<<dim3(2, 28, NNB), 128, SMEM_BYTES>>>(out);
}